// round 9
// baseline (speedup 1.0000x reference)
#include <cuda_runtime.h>
#include <cstdint>

// Problem constants
#define NB 8
#define NC 21
#define NW 512
#define NH 512
#define KK 5
#define KPAD 2
#define PLANE (NW * NH)

// 5-lane packing constants (6-bit lanes at bits 0,6,12,18,24; labels < 32)
#define LREP 0x01041041u
#define CADD 0x1F7DF7DFu
#define MBIT 0x20820820u

__device__ __forceinline__ unsigned int smem_u32(const void* p) {
    return (unsigned int)__cvta_generic_to_shared(p);
}
__device__ __forceinline__ void cp_async16(unsigned int dst, const void* src) {
    asm volatile("cp.async.cg.shared.global [%0], [%1], 16;\n"
                 :: "r"(dst), "l"(src) : "memory");
}
__device__ __forceinline__ void cp_commit() {
    asm volatile("cp.async.commit_group;\n" ::: "memory");
}
template <int N>
__device__ __forceinline__ void cp_wait() {
    asm volatile("cp.async.wait_group %0;\n" :: "n"(N) : "memory");
}

// Block: 128 threads, one row w, 4 contiguous h-pixels/thread.
// Grid: (NW, NB). All 21 channel rows staged via cp.async (register-free MLP).
__global__ __launch_bounds__(128)
void weight_matrix_kernel(const float* __restrict__ x,
                          const int*   __restrict__ y,
                          float*       __restrict__ out)
{
    // x stage: 21 channels x 512 floats (2KB each) = 42KB.
    __shared__ float4 xstage[NC][128];
    // packed y columns: rows w-2..w+2 in 6-bit lanes, col i-2 at index i.
    __shared__ unsigned int spack[520];          // 2080 B  (total 45088 B)

    const int w   = blockIdx.x;
    const int b   = blockIdx.y;
    const int tid = threadIdx.x;
    const int h0  = tid * 4;

    // ---- issue ALL channel loads up front (one commit group per channel) ----
    const float* xb = x + (size_t)(b * NC) * PLANE + w * NH + h0;
    #pragma unroll
    for (int c = 0; c < NC; c++) {
        cp_async16(smem_u32(&xstage[c][tid]), xb + (size_t)c * PLANE);
        cp_commit();
    }

    // ---- stage packed y columns (overlaps the async stream) ----
    const int* yb = y + b * PLANE;
    for (int i = tid; i < 520; i += 128) {
        const int gc = i - KPAD;
        unsigned int pack = 0;
        if (gc >= 0 && gc < NH) {
            #pragma unroll
            for (int r = 0; r < KK; r++) {
                const int gr = w - KPAD + r;
                unsigned int v = 0;
                if (gr >= 0 && gr < NW) v = (unsigned)__ldg(&yb[gr * NH + gc]);
                pack |= v << (6 * r);
            }
        }
        spack[i] = pack;
    }

    // ---- argmax over 21 channels from smem, paced by wait_group ----
    int bc0 = 0, bc1 = 0, bc2 = 0, bc3 = 0;
    cp_wait<NC - 1>();                       // channel 0 ready
    float4 best = xstage[0][tid];

    #pragma unroll
    for (int c = 1; c < NC; c++) {
        switch (c) {                          // wait_group needs an immediate
            case 1:  cp_wait<NC - 2>();  break;
            case 2:  cp_wait<NC - 3>();  break;
            case 3:  cp_wait<NC - 4>();  break;
            case 4:  cp_wait<NC - 5>();  break;
            case 5:  cp_wait<NC - 6>();  break;
            case 6:  cp_wait<NC - 7>();  break;
            case 7:  cp_wait<NC - 8>();  break;
            case 8:  cp_wait<NC - 9>();  break;
            case 9:  cp_wait<NC - 10>(); break;
            case 10: cp_wait<NC - 11>(); break;
            case 11: cp_wait<NC - 12>(); break;
            case 12: cp_wait<NC - 13>(); break;
            case 13: cp_wait<NC - 14>(); break;
            case 14: cp_wait<NC - 15>(); break;
            case 15: cp_wait<NC - 16>(); break;
            case 16: cp_wait<NC - 17>(); break;
            case 17: cp_wait<NC - 18>(); break;
            case 18: cp_wait<NC - 19>(); break;
            case 19: cp_wait<NC - 20>(); break;
            case 20: cp_wait<0>();       break;
        }
        const float4 v = xstage[c][tid];
        if (v.x > best.x) { best.x = v.x; bc0 = c; }
        if (v.y > best.y) { best.y = v.y; bc1 = c; }
        if (v.z > best.z) { best.z = v.z; bc2 = c; }
        if (v.w > best.w) { best.w = v.w; bc3 = c; }
    }

    // ---- barrier for spack (long since complete) ----
    __syncthreads();

    // ---- 5x5 mismatch count via packed lanes ----
    const uint4 lo = *reinterpret_cast<const uint4*>(&spack[h0]);
    const uint4 hi = *reinterpret_cast<const uint4*>(&spack[h0 + 4]);
    const unsigned int w0 = lo.x, w1 = lo.y, w2 = lo.z, w3 = lo.w;
    const unsigned int w4 = hi.x, w5 = hi.y, w6 = hi.z, w7 = hi.w;

    const unsigned int r0 = (unsigned)bc0 * LREP;
    const unsigned int r1 = (unsigned)bc1 * LREP;
    const unsigned int r2 = (unsigned)bc2 * LREP;
    const unsigned int r3 = (unsigned)bc3 * LREP;

    #define CNT(wd, rp) __popc((((wd) ^ (rp)) + CADD) & MBIT)
    const int cnt0 = CNT(w0,r0)+CNT(w1,r0)+CNT(w2,r0)+CNT(w3,r0)+CNT(w4,r0);
    const int cnt1 = CNT(w1,r1)+CNT(w2,r1)+CNT(w3,r1)+CNT(w4,r1)+CNT(w5,r1);
    const int cnt2 = CNT(w2,r2)+CNT(w3,r2)+CNT(w4,r2)+CNT(w5,r2)+CNT(w6,r2);
    const int cnt3 = CNT(w3,r3)+CNT(w4,r3)+CNT(w5,r3)+CNT(w6,r3)+CNT(w7,r3);
    #undef CNT

    float4 o;
    o.x = 1.0f + 1.5f * (float)cnt0;
    o.y = 1.0f + 1.5f * (float)cnt1;
    o.z = 1.0f + 1.5f * (float)cnt2;
    o.w = 1.0f + 1.5f * (float)cnt3;

    *reinterpret_cast<float4*>(out + (b * NW + w) * NH + h0) = o;
}

extern "C" void kernel_launch(void* const* d_in, const int* in_sizes, int n_in,
                              void* d_out, int out_size)
{
    const float* x = (const float*)d_in[0];
    const int*   y = (const int*)d_in[1];
    float*       o = (float*)d_out;

    dim3 grid(NW, NB);
    weight_matrix_kernel<<<grid, 128>>>(x, y, o);
}

// round 10
// speedup vs baseline: 1.2060x; 1.2060x over previous
#include <cuda_runtime.h>

// Problem constants
#define NB 8
#define NC 21
#define NW 512
#define NH 512
#define KK 5
#define KPAD 2
#define PLANE (NW * NH)

// 5-lane packing constants (6-bit lanes at bits 0,6,12,18,24; labels < 32)
#define LREP 0x01041041u   // 1 in each lane
#define CADD 0x1F7DF7DFu   // 31 in each lane
#define MBIT 0x20820820u   // bit5 of each lane

// Block: 256 threads, one row w, 2 contiguous h-pixels per thread (float2).
// Minimal per-thread state (~28 regs) -> thread-limited residency:
// 8 blocks/SM = 64 warps = 100% nominal occupancy.
// Grid: (NW, NB).
__global__ __launch_bounds__(256)
void weight_matrix_kernel(const float* __restrict__ x,
                          const int*   __restrict__ y,
                          float*       __restrict__ out)
{
    // spack[i] = labels of rows w-2..w+2 at global col (i-2), packed into
    // 6-bit lanes (row r -> bits 6r). Cols outside [0,512) pack to 0 (Unfold
    // zero padding; lane 0 mismatches any class c!=0, matching ref).
    __shared__ unsigned int spack[520];   // 2080 B

    const int w   = blockIdx.x;
    const int b   = blockIdx.y;
    const int tid = threadIdx.x;
    const int h0  = tid * 2;

    // ---- phase 1: stage packed column words (completes under the stream) ----
    const int* yb = y + b * PLANE;
    #pragma unroll
    for (int k = 0; k < 3; k++) {                  // 3*256 = 768 >= 520
        const int i = tid + k * 256;
        if (i < 520) {
            const int gc = i - KPAD;
            unsigned int pack = 0;
            if (gc >= 0 && gc < NH) {
                #pragma unroll
                for (int r = 0; r < KK; r++) {
                    const int gr = w - KPAD + r;
                    unsigned int v = 0;
                    if (gr >= 0 && gr < NW) v = (unsigned)__ldg(&yb[gr * NH + gc]);
                    pack |= v << (6 * r);
                }
            }
            spack[i] = pack;
        }
    }

    // ---- phase 2: argmax over 21 channels (float2; strict > => first idx) ----
    const float* xb = x + (size_t)(b * NC) * PLANE + w * NH + h0;
    float2 best = *reinterpret_cast<const float2*>(xb);
    int bc0 = 0, bc1 = 0;

    #pragma unroll 5
    for (int c = 1; c < NC; c++) {
        const float2 v = *reinterpret_cast<const float2*>(xb + c * PLANE);
        if (v.x > best.x) { best.x = v.x; bc0 = c; }
        if (v.y > best.y) { best.y = v.y; bc1 = c; }
    }

    // ---- barrier for spack (staging long since complete) ----
    __syncthreads();

    // ---- phase 3: 5x5 mismatch count via packed lanes ----
    // Pixel p (p=0,1) needs stored cols h0+p .. h0+p+4 -> words h0..h0+5.
    // h0 even -> &spack[h0] is 8B aligned: three LDS.64.
    const uint2 l0 = *reinterpret_cast<const uint2*>(&spack[h0]);
    const uint2 l1 = *reinterpret_cast<const uint2*>(&spack[h0 + 2]);
    const uint2 l2 = *reinterpret_cast<const uint2*>(&spack[h0 + 4]);
    const unsigned int w0 = l0.x, w1 = l0.y, w2 = l1.x;
    const unsigned int w3 = l1.y, w4 = l2.x, w5 = l2.y;

    const unsigned int r0 = (unsigned)bc0 * LREP;
    const unsigned int r1 = (unsigned)bc1 * LREP;

    // popc(((word ^ rep) + CADD) & MBIT) = # mismatching rows in that column
    #define CNT(wd, rp) __popc((((wd) ^ (rp)) + CADD) & MBIT)
    const int cnt0 = CNT(w0,r0)+CNT(w1,r0)+CNT(w2,r0)+CNT(w3,r0)+CNT(w4,r0);
    const int cnt1 = CNT(w1,r1)+CNT(w2,r1)+CNT(w3,r1)+CNT(w4,r1)+CNT(w5,r1);
    #undef CNT

    float2 o;
    o.x = 1.0f + 1.5f * (float)cnt0;
    o.y = 1.0f + 1.5f * (float)cnt1;

    *reinterpret_cast<float2*>(out + (b * NW + w) * NH + h0) = o;
}

extern "C" void kernel_launch(void* const* d_in, const int* in_sizes, int n_in,
                              void* d_out, int out_size)
{
    const float* x = (const float*)d_in[0];
    const int*   y = (const int*)d_in[1];
    float*       o = (float*)d_out;

    dim3 grid(NW, NB);
    weight_matrix_kernel<<<grid, 256>>>(x, y, o);
}

// round 11
// speedup vs baseline: 1.2754x; 1.0576x over previous
#include <cuda_runtime.h>

// Problem constants
#define NB 8
#define NC 21
#define NW 512
#define NH 512
#define KK 5
#define KPAD 2
#define PLANE (NW * NH)

// 5-lane packing constants (6-bit lanes at bits 0,6,12,18,24; labels < 32)
#define LREP 0x01041041u   // 1 in each lane
#define CADD 0x1F7DF7DFu   // 31 in each lane
#define MBIT 0x20820820u   // bit5 of each lane

// Block: 256 threads, one row w, 2 contiguous h-pixels per thread (float2).
// <=32 regs -> 8 blocks/SM = 2048 threads = 100% nominal occupancy.
// Channel loop unroll 7 -> 7 in-flight LDG.64 per warp.
// Grid: (NW, NB).
__global__ __launch_bounds__(256)
void weight_matrix_kernel(const float* __restrict__ x,
                          const int*   __restrict__ y,
                          float*       __restrict__ out)
{
    // spack[i] = labels of rows w-2..w+2 at global col (i-2), packed into
    // 6-bit lanes (row r -> bits 6r). Cols outside [0,512) pack to 0 (Unfold
    // zero padding; lane 0 mismatches any class c!=0, matching ref).
    __shared__ unsigned int spack[520];   // 2080 B

    const int w   = blockIdx.x;
    const int b   = blockIdx.y;
    const int tid = threadIdx.x;
    const int h0  = tid * 2;

    // ---- phase 1: stage packed column words (completes under the stream) ----
    const int* yb = y + b * PLANE;
    #pragma unroll
    for (int k = 0; k < 3; k++) {                  // 3*256 = 768 >= 520
        const int i = tid + k * 256;
        if (i < 520) {
            const int gc = i - KPAD;
            unsigned int pack = 0;
            if (gc >= 0 && gc < NH) {
                #pragma unroll
                for (int r = 0; r < KK; r++) {
                    const int gr = w - KPAD + r;
                    unsigned int v = 0;
                    if (gr >= 0 && gr < NW) v = (unsigned)__ldg(&yb[gr * NH + gc]);
                    pack |= v << (6 * r);
                }
            }
            spack[i] = pack;
        }
    }

    // ---- phase 2: argmax over 21 channels (float2; strict > => first idx) ----
    const float* xb = x + (size_t)(b * NC) * PLANE + w * NH + h0;
    float2 best = *reinterpret_cast<const float2*>(xb);
    int bc0 = 0, bc1 = 0;

    #pragma unroll 7
    for (int c = 1; c < NC; c++) {
        const float2 v = *reinterpret_cast<const float2*>(xb + c * PLANE);
        if (v.x > best.x) { best.x = v.x; bc0 = c; }
        if (v.y > best.y) { best.y = v.y; bc1 = c; }
    }

    // ---- barrier for spack (staging long since complete) ----
    __syncthreads();

    // ---- phase 3: 5x5 mismatch count via packed lanes ----
    // Pixel p (p=0,1) needs stored cols h0+p .. h0+p+4 -> words h0..h0+5.
    // h0 even -> &spack[h0] is 8B aligned: three LDS.64.
    const uint2 l0 = *reinterpret_cast<const uint2*>(&spack[h0]);
    const uint2 l1 = *reinterpret_cast<const uint2*>(&spack[h0 + 2]);
    const uint2 l2 = *reinterpret_cast<const uint2*>(&spack[h0 + 4]);
    const unsigned int w0 = l0.x, w1 = l0.y, w2 = l1.x;
    const unsigned int w3 = l1.y, w4 = l2.x, w5 = l2.y;

    const unsigned int r0 = (unsigned)bc0 * LREP;
    const unsigned int r1 = (unsigned)bc1 * LREP;

    // popc(((word ^ rep) + CADD) & MBIT) = # mismatching rows in that column
    #define CNT(wd, rp) __popc((((wd) ^ (rp)) + CADD) & MBIT)
    const int cnt0 = CNT(w0,r0)+CNT(w1,r0)+CNT(w2,r0)+CNT(w3,r0)+CNT(w4,r0);
    const int cnt1 = CNT(w1,r1)+CNT(w2,r1)+CNT(w3,r1)+CNT(w4,r1)+CNT(w5,r1);
    #undef CNT

    float2 o;
    o.x = 1.0f + 1.5f * (float)cnt0;
    o.y = 1.0f + 1.5f * (float)cnt1;

    *reinterpret_cast<float2*>(out + (b * NW + w) * NH + h0) = o;
}

extern "C" void kernel_launch(void* const* d_in, const int* in_sizes, int n_in,
                              void* d_out, int out_size)
{
    const float* x = (const float*)d_in[0];
    const int*   y = (const int*)d_in[1];
    float*       o = (float*)d_out;

    dim3 grid(NW, NB);
    weight_matrix_kernel<<<grid, 256>>>(x, y, o);
}